// round 14
// baseline (speedup 1.0000x reference)
#include <cuda_runtime.h>
#include <cuda_bf16.h>
#include <math.h>
#include <stdint.h>

typedef unsigned long long u64;
typedef unsigned int u32;

// Problem constants
#define NROWS   65536      // 32*2048 flattened z rows
#define EDIM    256
#define NE      1024
#define LOSSPARTS 8192
#define MARGIN  4e-3f      // rescore margin (worst-case bf16 approx error ~5e-4)
#define CAP     96         // candidate list capacity per row

// Full-concat output layout (tuple order: loss, z_q_st, idx, perplexity, N_t, m_t)
#define OFF_LOSS 0
#define OFF_ZQ   1
#define OFF_IDX  16777217
#define OFF_PERP 16842753
#define OFF_NT   16842754
#define OFF_MT   16843778

// ---------------- scratch (__device__ globals: no allocations allowed) ----------
__device__ int    g_idx[NROWS];
__device__ float  g_rowa[NROWS];        // fl32(||z_row||^2)
__device__ float  g_enorm[NE];          // fl32(||e_j||^2)
__device__ float  g_counts[NE];
__device__ float  g_sums[NE * EDIM];
__device__ double g_losspart[LOSSPARTS];
__device__ u32    g_bmin[NROWS];        // running approx min (float bits)
__device__ u32    g_ccnt[NROWS];        // candidate counts
__device__ u32    g_cand[NROWS * CAP];  // candidate code lists
// bf16 hi parts
__device__ __nv_bfloat16 g_zh[NROWS * EDIM];
__device__ __nv_bfloat16 g_eh[NE * EDIM];

// ---------------- PTX helpers ----------------------------------------------------
__device__ __forceinline__ u32 smem_u32(const void* p) {
    u32 a;
    asm("{ .reg .u64 t; cvta.to.shared.u64 t, %1; cvt.u32.u64 %0, t; }" : "=r"(a) : "l"(p));
    return a;
}
__device__ __forceinline__ void ldmx4(u32* r, u32 addr) {
    asm volatile("ldmatrix.sync.aligned.m8n8.x4.shared.b16 {%0,%1,%2,%3}, [%4];"
                 : "=r"(r[0]), "=r"(r[1]), "=r"(r[2]), "=r"(r[3]) : "r"(addr));
}
__device__ __forceinline__ void mma_bf16(float* c, const u32* a, const u32* b) {
    asm volatile(
        "mma.sync.aligned.m16n8k16.row.col.f32.bf16.bf16.f32 "
        "{%0,%1,%2,%3}, {%4,%5,%6,%7}, {%8,%9}, {%0,%1,%2,%3};"
        : "+f"(c[0]), "+f"(c[1]), "+f"(c[2]), "+f"(c[3])
        : "r"(a[0]), "r"(a[1]), "r"(a[2]), "r"(a[3]), "r"(b[0]), "r"(b[1]));
}
__device__ __forceinline__ u64 pack_bf4(const float* f) {
    unsigned short h0 = __bfloat16_as_ushort(__float2bfloat16(f[0]));
    unsigned short h1 = __bfloat16_as_ushort(__float2bfloat16(f[1]));
    unsigned short h2 = __bfloat16_as_ushort(__float2bfloat16(f[2]));
    unsigned short h3 = __bfloat16_as_ushort(__float2bfloat16(f[3]));
    return (u64)h0 | ((u64)h1 << 16) | ((u64)h2 << 32) | ((u64)h3 << 48);
}

// ---------------- kernel: zero / init --------------------------------------------
__global__ void zero_kernel() {
    int i = blockIdx.x * blockDim.x + threadIdx.x;     // grid covers 262144
    if (i < NE * EDIM) g_sums[i] = 0.0f;
    if (i < NE)        g_counts[i] = 0.0f;
    if (i < LOSSPARTS) g_losspart[i] = 0.0;
    if (i < NROWS)   { g_bmin[i] = 0x7F800000u; g_ccnt[i] = 0u; }
}

// ---------------- kernel: z prep — row norms + bf16 split (warp per row) --------
__global__ void prep_z_kernel(const float* __restrict__ z) {
    int tid  = threadIdx.x;
    int lane = tid & 31;
    int row  = blockIdx.x * 8 + (tid >> 5);
    const float4* zr = reinterpret_cast<const float4*>(z + (size_t)row * EDIM);
    double s = 0.0;
    #pragma unroll
    for (int j = 0; j < 2; ++j) {
        int c4 = lane + 32 * j;
        float4 v = zr[c4];
        float f[4] = { v.x, v.y, v.z, v.w };
        s += (double)v.x * v.x; s += (double)v.y * v.y;
        s += (double)v.z * v.z; s += (double)v.w * v.w;
        *reinterpret_cast<u64*>(g_zh + (size_t)row * EDIM + c4 * 4) = pack_bf4(f);
    }
    #pragma unroll
    for (int off = 16; off; off >>= 1)
        s += __shfl_down_sync(0xffffffffu, s, off);
    if (lane == 0) g_rowa[row] = (float)s;
}

// ---------------- kernel: e prep — code norms + bf16 split (warp per row) -------
__global__ void prep_e_kernel(const float* __restrict__ emb) {
    int tid  = threadIdx.x;
    int lane = tid & 31;
    int row  = blockIdx.x * 8 + (tid >> 5);
    if (row >= NE) return;
    const float4* er = reinterpret_cast<const float4*>(emb + (size_t)row * EDIM);
    double s = 0.0;
    #pragma unroll
    for (int j = 0; j < 2; ++j) {
        int c4 = lane + 32 * j;
        float4 v = er[c4];
        float f[4] = { v.x, v.y, v.z, v.w };
        s += (double)v.x * v.x; s += (double)v.y * v.y;
        s += (double)v.z * v.z; s += (double)v.w * v.w;
        *reinterpret_cast<u64*>(g_eh + (size_t)row * EDIM + c4 * 4) = pack_bf4(f);
    }
    #pragma unroll
    for (int off = 16; off; off >>= 1)
        s += __shfl_down_sync(0xffffffffu, s, off);
    if (lane == 0) g_enorm[row] = (float)s;
}

// ---------------- kernel: approx bf16 MMA filter --------------------------------
// Grid (512, 8): blockIdx.x = 128-row tile (fast dim), blockIdx.y = 128-code tile
// (slow dim) -> code tiles execute roughly sequentially, so the running global
// min in g_bmin is tight when later tiles collect candidates.
// 256 threads = 8 warps as 4(m) x 2(n); warp tile 32 rows x 64 codes.
__global__ __launch_bounds__(256, 2)
void argmin_mma_kernel() {
    __shared__ __align__(16) unsigned short sAh[128 * 40];
    __shared__ __align__(16) unsigned short sBh[128 * 40];
    __shared__ u32 rowmin[128];

    const int tid  = threadIdx.x;
    const int lane = tid & 31;
    const int warp = tid >> 5;
    const int wm = warp >> 1;            // 0..3
    const int wn = warp & 1;             // 0..1
    const int R = blockIdx.x * 128;
    const int C = blockIdx.y * 128;

    if (tid < 128) rowmin[tid] = 0x7F800000u;

    float acc[2][8][4];
    #pragma unroll
    for (int mt = 0; mt < 2; ++mt)
        #pragma unroll
        for (int nt = 0; nt < 8; ++nt)
            #pragma unroll
            for (int j = 0; j < 4; ++j) acc[mt][nt][j] = 0.0f;

    const int a_m = ((lane >> 3) & 1) * 8 + (lane & 7);
    const int a_k = (lane >> 4) * 8;
    const int b_n = (lane >> 4) * 8 + (lane & 7);
    const int b_k = ((lane >> 3) & 1) * 8;

    const u32 sAh_b = smem_u32(sAh);
    const u32 sBh_b = smem_u32(sBh);

    const int a_row = tid >> 2, a_q = tid & 3;
    for (int kt = 0; kt < 8; ++kt) {
        __syncthreads();
        #pragma unroll
        for (int i = 0; i < 2; ++i) {
            int row = a_row + i * 64;
            const float4* ph = reinterpret_cast<const float4*>(
                g_zh + (size_t)(R + row) * EDIM + kt * 32) + a_q;
            *reinterpret_cast<float4*>(sAh + row * 40 + a_q * 8) = *ph;
            const float4* pb = reinterpret_cast<const float4*>(
                g_eh + (size_t)(C + row) * EDIM + kt * 32) + a_q;
            *reinterpret_cast<float4*>(sBh + row * 40 + a_q * 8) = *pb;
        }
        __syncthreads();

        #pragma unroll
        for (int k16 = 0; k16 < 2; ++k16) {
            const int kb = k16 * 16;
            u32 ah[2][4], bh[4][4];
            #pragma unroll
            for (int mt = 0; mt < 2; ++mt) {
                u32 off = (u32)(((wm * 32 + mt * 16 + a_m) * 40 + kb + a_k) * 2);
                ldmx4(ah[mt], sAh_b + off);
            }
            #pragma unroll
            for (int h = 0; h < 4; ++h) {
                u32 off = (u32)(((wn * 64 + h * 16 + b_n) * 40 + kb + b_k) * 2);
                ldmx4(bh[h], sBh_b + off);
            }
            #pragma unroll
            for (int mt = 0; mt < 2; ++mt)
                #pragma unroll
                for (int nt = 0; nt < 8; ++nt)
                    mma_bf16(acc[mt][nt], ah[mt], &bh[nt >> 1][(nt & 1) * 2]);
        }
    }

    // ---------------- epilogue --------------------------------------------------
    const int tq = lane >> 2, tr = lane & 3;
    float bb[8][2];
    #pragma unroll
    for (int nt = 0; nt < 8; ++nt) {
        int c0 = C + wn * 64 + nt * 8 + tr * 2;
        bb[nt][0] = g_enorm[c0];
        bb[nt][1] = g_enorm[c0 + 1];
    }
    float areg[4];
    #pragma unroll
    for (int j = 0; j < 4; ++j) areg[j] = g_rowa[R + wm * 32 + j * 8 + tq];

    // step1: per-row tile min -> smem
    #pragma unroll
    for (int mt = 0; mt < 2; ++mt) {
        float m0 = __int_as_float(0x7f800000), m1 = m0;
        #pragma unroll
        for (int nt = 0; nt < 8; ++nt) {
            float d00 = (areg[mt * 2]     + bb[nt][0]) - 2.0f * acc[mt][nt][0];
            float d01 = (areg[mt * 2]     + bb[nt][1]) - 2.0f * acc[mt][nt][1];
            float d10 = (areg[mt * 2 + 1] + bb[nt][0]) - 2.0f * acc[mt][nt][2];
            float d11 = (areg[mt * 2 + 1] + bb[nt][1]) - 2.0f * acc[mt][nt][3];
            m0 = fminf(m0, fminf(d00, d01));
            m1 = fminf(m1, fminf(d10, d11));
        }
        #pragma unroll
        for (int off = 1; off < 4; off <<= 1) {
            m0 = fminf(m0, __shfl_xor_sync(0xffffffffu, m0, off));
            m1 = fminf(m1, __shfl_xor_sync(0xffffffffu, m1, off));
        }
        if (tr == 0) {
            atomicMin(&rowmin[wm * 32 + mt * 16 + tq],     __float_as_uint(m0));
            atomicMin(&rowmin[wm * 32 + mt * 16 + tq + 8], __float_as_uint(m1));
        }
    }
    __syncthreads();

    // step2: fold into running global min (one thread per row)
    if (wn == 0 && tr == 0) {
        #pragma unroll
        for (int mt = 0; mt < 2; ++mt) {
            #pragma unroll
            for (int h = 0; h < 2; ++h) {
                int rl = wm * 32 + mt * 16 + tq + h * 8;
                u32 own = rowmin[rl];
                u32 old = atomicMin(&g_bmin[R + rl], own);
                rowmin[rl] = own < old ? own : old;
            }
        }
    }
    __syncthreads();

    // step3: collect candidates vs running-min threshold (superset-safe: the
    // running min only decreases, so every set collected is a superset of the
    // final-threshold set; overflow falls back to an exact full scan)
    #pragma unroll
    for (int mt = 0; mt < 2; ++mt) {
        int r0 = wm * 32 + mt * 16 + tq, r1 = r0 + 8;
        float thr0 = __uint_as_float(rowmin[r0]) + MARGIN;
        float thr1 = __uint_as_float(rowmin[r1]) + MARGIN;
        #pragma unroll
        for (int nt = 0; nt < 8; ++nt) {
            int c0 = C + wn * 64 + nt * 8 + tr * 2;
            float d00 = (areg[mt * 2]     + bb[nt][0]) - 2.0f * acc[mt][nt][0];
            float d01 = (areg[mt * 2]     + bb[nt][1]) - 2.0f * acc[mt][nt][1];
            float d10 = (areg[mt * 2 + 1] + bb[nt][0]) - 2.0f * acc[mt][nt][2];
            float d11 = (areg[mt * 2 + 1] + bb[nt][1]) - 2.0f * acc[mt][nt][3];
            if (d00 <= thr0) { u32 p = atomicAdd(&g_ccnt[R + r0], 1u); if (p < CAP) g_cand[(R + r0) * CAP + p] = (u32)c0; }
            if (d01 <= thr0) { u32 p = atomicAdd(&g_ccnt[R + r0], 1u); if (p < CAP) g_cand[(R + r0) * CAP + p] = (u32)(c0 + 1); }
            if (d10 <= thr1) { u32 p = atomicAdd(&g_ccnt[R + r1], 1u); if (p < CAP) g_cand[(R + r1) * CAP + p] = (u32)c0; }
            if (d11 <= thr1) { u32 p = atomicAdd(&g_ccnt[R + r1], 1u); if (p < CAP) g_cand[(R + r1) * CAP + p] = (u32)(c0 + 1); }
        }
    }
}

// ---------------- kernel: exact rescore + scatter (warp per row) ----------------
__global__ __launch_bounds__(256, 4)
void rescore_scatter_kernel(const float* __restrict__ z, const float* __restrict__ emb,
                            float* __restrict__ out, int out_size,
                            int zq_off, int idx_off) {
    __shared__ double wsum[8];
    const int tid  = threadIdx.x;
    const int lane = tid & 31;
    const int w    = tid >> 5;
    const int row  = blockIdx.x * 8 + w;

    const float a = g_rowa[row];
    const float* zr = z + (size_t)row * EDIM;
    u32 cnt = g_ccnt[row];
    u64 best = ~0ull;
    if (cnt <= CAP) {
        for (int c = lane; c < (int)cnt; c += 32) {
            int code = g_cand[row * CAP + c];
            const float* er = emb + (size_t)code * EDIM;
            float m = 0.0f;
            #pragma unroll 8
            for (int k = 0; k < EDIM; ++k) m = fmaf(zr[k], er[k], m);
            float d = (a + g_enorm[code]) - 2.0f * m;
            u64 p = ((u64)__float_as_uint(d) << 32) | (u32)code;
            if (p < best) best = p;
        }
    } else {
        // overflow fallback: exact scan of all 1024 codes (rare)
        for (int code = lane; code < NE; code += 32) {
            const float* er = emb + (size_t)code * EDIM;
            float m = 0.0f;
            #pragma unroll 8
            for (int k = 0; k < EDIM; ++k) m = fmaf(zr[k], er[k], m);
            float d = (a + g_enorm[code]) - 2.0f * m;
            u64 p = ((u64)__float_as_uint(d) << 32) | (u32)code;
            if (p < best) best = p;
        }
    }
    #pragma unroll
    for (int off = 16; off; off >>= 1) {
        u64 o = __shfl_xor_sync(0xffffffffu, best, off);
        if (o < best) best = o;
    }
    const int id = (int)(u32)(best & 0xffffffffull);

    // scatter: z_q straight-through, loss partial, segment sums, counts
    const float4* zr4 = reinterpret_cast<const float4*>(zr);
    const float4* er4 = reinterpret_cast<const float4*>(emb + (size_t)id * EDIM);
    double ls = 0.0;
    #pragma unroll
    for (int j = 0; j < 2; ++j) {
        int c4 = lane + 32 * j;
        float4 zv = zr4[c4];
        float4 ev = er4[c4];
        float dx = ev.x - zv.x, dy = ev.y - zv.y, dz = ev.z - zv.z, dw = ev.w - zv.w;
        if (zq_off >= 0) {
            int base = zq_off + row * EDIM + c4 * 4;
            if (base + 3 < out_size) {
                out[base + 0] = zv.x + dx;
                out[base + 1] = zv.y + dy;
                out[base + 2] = zv.z + dz;
                out[base + 3] = zv.w + dw;
            }
        }
        ls += (double)dx * dx + (double)dy * dy + (double)dz * dz + (double)dw * dw;
        int sb = id * EDIM + c4 * 4;
        atomicAdd(&g_sums[sb + 0], zv.x);
        atomicAdd(&g_sums[sb + 1], zv.y);
        atomicAdd(&g_sums[sb + 2], zv.z);
        atomicAdd(&g_sums[sb + 3], zv.w);
    }
    if (lane == 0) {
        g_idx[row] = id;
        atomicAdd(&g_counts[id], 1.0f);
        if (idx_off >= 0) {
            int p = idx_off + row;
            if (p < out_size) out[p] = (float)id;
        }
    }
    #pragma unroll
    for (int off = 16; off; off >>= 1)
        ls += __shfl_down_sync(0xffffffffu, ls, off);
    if (lane == 0) wsum[w] = ls;
    __syncthreads();
    if (tid == 0) {
        double t = 0.0;
        #pragma unroll
        for (int i = 0; i < 8; ++i) t += wsum[i];
        g_losspart[blockIdx.x] = t;
    }
}

// ---------------- kernel: m_t EMA update ---------------------------------------
__global__ void mt_kernel(const float* __restrict__ m_t, float* __restrict__ out,
                          int out_size, int mt_off) {
    int i = blockIdx.x * blockDim.x + threadIdx.x;
    if (i >= NE * EDIM || mt_off < 0) return;
    int j = i >> 8;
    float m = m_t[i];
    float val = (g_counts[j] > 0.0f) ? (m * 0.99f + g_sums[i] * 0.01f) : m;
    int p = mt_off + i;
    if (p < out_size) out[p] = val;
}

// ---------------- kernel: loss / perplexity / N_t -------------------------------
__global__ void finalize_kernel(const float* __restrict__ N_t, float* __restrict__ out,
                                int out_size, int loss_off, int perp_off, int nt_off) {
    __shared__ double red[1024];
    int tid = threadIdx.x;

    double s = 0.0;
    for (int i = tid; i < LOSSPARTS; i += 1024) s += g_losspart[i];
    red[tid] = s;
    __syncthreads();
    for (int st = 512; st > 0; st >>= 1) {
        if (tid < st) red[tid] += red[tid + st];
        __syncthreads();
    }
    double loss_sum = red[0];
    __syncthreads();

    float c = g_counts[tid];
    float em = c * (1.0f / 65536.0f);
    red[tid] = (double)(em * logf(em + 1e-10f));
    __syncthreads();
    for (int st = 512; st > 0; st >>= 1) {
        if (tid < st) red[tid] += red[tid + st];
        __syncthreads();
    }
    if (tid == 0) {
        if (loss_off >= 0 && loss_off < out_size)
            out[loss_off] = 0.25f * (float)(loss_sum / 16777216.0);
        if (perp_off >= 0 && perp_off < out_size)
            out[perp_off] = expf(-(float)red[0]);
    }
    if (nt_off >= 0) {
        float nt = N_t[tid];
        float val = (c > 0.0f) ? (nt * 0.99f + c * 0.01f) : nt;
        int p = nt_off + tid;
        if (p < out_size) out[p] = val;
    }
}

// ---------------- launcher -------------------------------------------------------
extern "C" void kernel_launch(void* const* d_in, const int* in_sizes, int n_in,
                              void* d_out, int out_size) {
    const float* z   = (const float*)d_in[0];   // [32,2048,256]
    const float* emb = (const float*)d_in[1];   // [1024,256]
    const float* N_t = (const float*)d_in[2];   // [1024]
    const float* m_t = (const float*)d_in[3];   // [1024,256]
    float* out = (float*)d_out;

    int loss_off, zq_off, idx_off, perp_off, nt_off, mt_off;
    if (out_size == NROWS * EDIM) {             // z_q_st only
        loss_off = -1; zq_off = 0; idx_off = -1; perp_off = -1; nt_off = -1; mt_off = -1;
    } else if (out_size == NROWS) {             // idx only
        loss_off = -1; zq_off = -1; idx_off = 0; perp_off = -1; nt_off = -1; mt_off = -1;
    } else {                                    // full tuple concat
        loss_off = OFF_LOSS; zq_off = OFF_ZQ; idx_off = OFF_IDX;
        perp_off = OFF_PERP; nt_off = OFF_NT; mt_off = OFF_MT;
    }

    zero_kernel<<<1024, 256>>>();
    prep_e_kernel<<<NE / 8, 256>>>(emb);
    prep_z_kernel<<<NROWS / 8, 256>>>(z);
    {
        dim3 grid(512, 8);                      // row tiles fast, code tiles slow
        argmin_mma_kernel<<<grid, 256>>>();
    }
    rescore_scatter_kernel<<<NROWS / 8, 256>>>(z, emb, out, out_size, zq_off, idx_off);
    mt_kernel<<<NE * EDIM / 256, 256>>>(m_t, out, out_size, mt_off);
    finalize_kernel<<<1, 1024>>>(N_t, out, out_size, loss_off, perp_off, nt_off);
}

// round 15
// speedup vs baseline: 1.7359x; 1.7359x over previous
#include <cuda_runtime.h>
#include <cuda_bf16.h>
#include <math.h>
#include <stdint.h>

typedef unsigned long long u64;
typedef unsigned int u32;

// Problem constants
#define NROWS   65536      // 32*2048 flattened z rows
#define EDIM    256
#define NE      1024
#define LOSSPARTS 8192
#define MARGIN  2.5e-3f    // rescore margin (worst-case approx error ~1e-3)
#define CAP     128        // candidate list capacity per row

// Full-concat output layout (tuple order: loss, z_q_st, idx, perplexity, N_t, m_t)
#define OFF_LOSS 0
#define OFF_ZQ   1
#define OFF_IDX  16777217
#define OFF_PERP 16842753
#define OFF_NT   16842754
#define OFF_MT   16843778

// ---------------- scratch (__device__ globals: no allocations allowed) ----------
__device__ int    g_idx[NROWS];
__device__ float  g_rowa[NROWS];        // fl32(||z_row||^2)
__device__ float  g_enorm[NE];          // fl32(||e_j||^2)
__device__ float  g_counts[NE];
__device__ float  g_sums[NE * EDIM];
__device__ double g_losspart[LOSSPARTS];
__device__ u32    g_bmin[NROWS];        // running approx min (float bits)
__device__ u32    g_ccnt[NROWS];        // candidate counts
__device__ u32    g_cand[NROWS * CAP];  // candidate code lists
// bf16 hi parts
__device__ __nv_bfloat16 g_zh[NROWS * EDIM];
__device__ __nv_bfloat16 g_eh[NE * EDIM];

// ---------------- PTX helpers ----------------------------------------------------
__device__ __forceinline__ u32 smem_u32(const void* p) {
    u32 a;
    asm("{ .reg .u64 t; cvta.to.shared.u64 t, %1; cvt.u32.u64 %0, t; }" : "=r"(a) : "l"(p));
    return a;
}
__device__ __forceinline__ void ldmx4(u32* r, u32 addr) {
    asm volatile("ldmatrix.sync.aligned.m8n8.x4.shared.b16 {%0,%1,%2,%3}, [%4];"
                 : "=r"(r[0]), "=r"(r[1]), "=r"(r[2]), "=r"(r[3]) : "r"(addr));
}
__device__ __forceinline__ void mma_bf16(float* c, const u32* a, const u32* b) {
    asm volatile(
        "mma.sync.aligned.m16n8k16.row.col.f32.bf16.bf16.f32 "
        "{%0,%1,%2,%3}, {%4,%5,%6,%7}, {%8,%9}, {%0,%1,%2,%3};"
        : "+f"(c[0]), "+f"(c[1]), "+f"(c[2]), "+f"(c[3])
        : "r"(a[0]), "r"(a[1]), "r"(a[2]), "r"(a[3]), "r"(b[0]), "r"(b[1]));
}
__device__ __forceinline__ u64 pack_bf4(const float* f) {
    unsigned short h0 = __bfloat16_as_ushort(__float2bfloat16(f[0]));
    unsigned short h1 = __bfloat16_as_ushort(__float2bfloat16(f[1]));
    unsigned short h2 = __bfloat16_as_ushort(__float2bfloat16(f[2]));
    unsigned short h3 = __bfloat16_as_ushort(__float2bfloat16(f[3]));
    return (u64)h0 | ((u64)h1 << 16) | ((u64)h2 << 32) | ((u64)h3 << 48);
}

// ---------------- kernel: zero / init --------------------------------------------
__global__ void zero_kernel() {
    int i = blockIdx.x * blockDim.x + threadIdx.x;     // grid covers 262144
    if (i < NE * EDIM) g_sums[i] = 0.0f;
    if (i < NE)        g_counts[i] = 0.0f;
    if (i < LOSSPARTS) g_losspart[i] = 0.0;
    if (i < NROWS)   { g_bmin[i] = 0x7F800000u; g_ccnt[i] = 0u; }
}

// ---------------- kernel: z prep — row norms + bf16 split (warp per row) --------
__global__ void prep_z_kernel(const float* __restrict__ z) {
    int tid  = threadIdx.x;
    int lane = tid & 31;
    int row  = blockIdx.x * 8 + (tid >> 5);
    const float4* zr = reinterpret_cast<const float4*>(z + (size_t)row * EDIM);
    double s = 0.0;
    #pragma unroll
    for (int j = 0; j < 2; ++j) {
        int c4 = lane + 32 * j;
        float4 v = zr[c4];
        float f[4] = { v.x, v.y, v.z, v.w };
        s += (double)v.x * v.x; s += (double)v.y * v.y;
        s += (double)v.z * v.z; s += (double)v.w * v.w;
        *reinterpret_cast<u64*>(g_zh + (size_t)row * EDIM + c4 * 4) = pack_bf4(f);
    }
    #pragma unroll
    for (int off = 16; off; off >>= 1)
        s += __shfl_down_sync(0xffffffffu, s, off);
    if (lane == 0) g_rowa[row] = (float)s;
}

// ---------------- kernel: e prep — code norms + bf16 split (warp per row) -------
__global__ void prep_e_kernel(const float* __restrict__ emb) {
    int tid  = threadIdx.x;
    int lane = tid & 31;
    int row  = blockIdx.x * 8 + (tid >> 5);
    if (row >= NE) return;
    const float4* er = reinterpret_cast<const float4*>(emb + (size_t)row * EDIM);
    double s = 0.0;
    #pragma unroll
    for (int j = 0; j < 2; ++j) {
        int c4 = lane + 32 * j;
        float4 v = er[c4];
        float f[4] = { v.x, v.y, v.z, v.w };
        s += (double)v.x * v.x; s += (double)v.y * v.y;
        s += (double)v.z * v.z; s += (double)v.w * v.w;
        *reinterpret_cast<u64*>(g_eh + (size_t)row * EDIM + c4 * 4) = pack_bf4(f);
    }
    #pragma unroll
    for (int off = 16; off; off >>= 1)
        s += __shfl_down_sync(0xffffffffu, s, off);
    if (lane == 0) g_enorm[row] = (float)s;
}

// ---------------- kernel: approx bf16 MMA filter --------------------------------
// Grid (8, 512): blockIdx.x = 128-code tile, blockIdx.y = 128-row tile.
// 256 threads = 8 warps as 4(m) x 2(n); warp tile 32 rows x 64 codes.
// Per row: tile min -> fold into running global min -> collect candidates within
// MARGIN of the folded min (superset of the final-threshold set; overflow ->
// exact full-scan fallback in rescore).
__global__ __launch_bounds__(256, 2)
void argmin_mma_kernel() {
    __shared__ __align__(16) unsigned short sAh[128 * 40];
    __shared__ __align__(16) unsigned short sBh[128 * 40];
    __shared__ u32 rowmin[128];

    const int tid  = threadIdx.x;
    const int lane = tid & 31;
    const int warp = tid >> 5;
    const int wm = warp >> 1;            // 0..3
    const int wn = warp & 1;             // 0..1
    const int R = blockIdx.y * 128;
    const int C = blockIdx.x * 128;

    if (tid < 128) rowmin[tid] = 0x7F800000u;

    float acc[2][8][4];
    #pragma unroll
    for (int mt = 0; mt < 2; ++mt)
        #pragma unroll
        for (int nt = 0; nt < 8; ++nt)
            #pragma unroll
            for (int j = 0; j < 4; ++j) acc[mt][nt][j] = 0.0f;

    const int a_m = ((lane >> 3) & 1) * 8 + (lane & 7);
    const int a_k = (lane >> 4) * 8;
    const int b_n = (lane >> 4) * 8 + (lane & 7);
    const int b_k = ((lane >> 3) & 1) * 8;

    const u32 sAh_b = smem_u32(sAh);
    const u32 sBh_b = smem_u32(sBh);

    const int a_row = tid >> 2, a_q = tid & 3;
    for (int kt = 0; kt < 8; ++kt) {
        __syncthreads();
        #pragma unroll
        for (int i = 0; i < 2; ++i) {
            int row = a_row + i * 64;
            const float4* ph = reinterpret_cast<const float4*>(
                g_zh + (size_t)(R + row) * EDIM + kt * 32) + a_q;
            *reinterpret_cast<float4*>(sAh + row * 40 + a_q * 8) = *ph;
            const float4* pb = reinterpret_cast<const float4*>(
                g_eh + (size_t)(C + row) * EDIM + kt * 32) + a_q;
            *reinterpret_cast<float4*>(sBh + row * 40 + a_q * 8) = *pb;
        }
        __syncthreads();

        #pragma unroll
        for (int k16 = 0; k16 < 2; ++k16) {
            const int kb = k16 * 16;
            u32 ah[2][4], bh[4][4];
            #pragma unroll
            for (int mt = 0; mt < 2; ++mt) {
                u32 off = (u32)(((wm * 32 + mt * 16 + a_m) * 40 + kb + a_k) * 2);
                ldmx4(ah[mt], sAh_b + off);
            }
            #pragma unroll
            for (int h = 0; h < 4; ++h) {
                u32 off = (u32)(((wn * 64 + h * 16 + b_n) * 40 + kb + b_k) * 2);
                ldmx4(bh[h], sBh_b + off);
            }
            #pragma unroll
            for (int mt = 0; mt < 2; ++mt)
                #pragma unroll
                for (int nt = 0; nt < 8; ++nt)
                    mma_bf16(acc[mt][nt], ah[mt], &bh[nt >> 1][(nt & 1) * 2]);
        }
    }

    // ---------------- epilogue --------------------------------------------------
    const int tq = lane >> 2, tr = lane & 3;
    float bb[8][2];
    #pragma unroll
    for (int nt = 0; nt < 8; ++nt) {
        int c0 = C + wn * 64 + nt * 8 + tr * 2;
        bb[nt][0] = g_enorm[c0];
        bb[nt][1] = g_enorm[c0 + 1];
    }
    float areg[4];
    #pragma unroll
    for (int j = 0; j < 4; ++j) areg[j] = g_rowa[R + wm * 32 + j * 8 + tq];

    // step1: per-row tile min -> smem
    #pragma unroll
    for (int mt = 0; mt < 2; ++mt) {
        float m0 = __int_as_float(0x7f800000), m1 = m0;
        #pragma unroll
        for (int nt = 0; nt < 8; ++nt) {
            float d00 = (areg[mt * 2]     + bb[nt][0]) - 2.0f * acc[mt][nt][0];
            float d01 = (areg[mt * 2]     + bb[nt][1]) - 2.0f * acc[mt][nt][1];
            float d10 = (areg[mt * 2 + 1] + bb[nt][0]) - 2.0f * acc[mt][nt][2];
            float d11 = (areg[mt * 2 + 1] + bb[nt][1]) - 2.0f * acc[mt][nt][3];
            m0 = fminf(m0, fminf(d00, d01));
            m1 = fminf(m1, fminf(d10, d11));
        }
        #pragma unroll
        for (int off = 1; off < 4; off <<= 1) {
            m0 = fminf(m0, __shfl_xor_sync(0xffffffffu, m0, off));
            m1 = fminf(m1, __shfl_xor_sync(0xffffffffu, m1, off));
        }
        if (tr == 0) {
            atomicMin(&rowmin[wm * 32 + mt * 16 + tq],     __float_as_uint(m0));
            atomicMin(&rowmin[wm * 32 + mt * 16 + tq + 8], __float_as_uint(m1));
        }
    }
    __syncthreads();

    // step2: fold into running global min (one thread per row)
    if (wn == 0 && tr == 0) {
        #pragma unroll
        for (int mt = 0; mt < 2; ++mt) {
            #pragma unroll
            for (int h = 0; h < 2; ++h) {
                int rl = wm * 32 + mt * 16 + tq + h * 8;
                u32 own = rowmin[rl];
                u32 old = atomicMin(&g_bmin[R + rl], own);
                rowmin[rl] = own < old ? own : old;
            }
        }
    }
    __syncthreads();

    // step3: collect candidates vs running-min threshold (superset-safe)
    #pragma unroll
    for (int mt = 0; mt < 2; ++mt) {
        int r0 = wm * 32 + mt * 16 + tq, r1 = r0 + 8;
        float thr0 = __uint_as_float(rowmin[r0]) + MARGIN;
        float thr1 = __uint_as_float(rowmin[r1]) + MARGIN;
        #pragma unroll
        for (int nt = 0; nt < 8; ++nt) {
            int c0 = C + wn * 64 + nt * 8 + tr * 2;
            float d00 = (areg[mt * 2]     + bb[nt][0]) - 2.0f * acc[mt][nt][0];
            float d01 = (areg[mt * 2]     + bb[nt][1]) - 2.0f * acc[mt][nt][1];
            float d10 = (areg[mt * 2 + 1] + bb[nt][0]) - 2.0f * acc[mt][nt][2];
            float d11 = (areg[mt * 2 + 1] + bb[nt][1]) - 2.0f * acc[mt][nt][3];
            if (d00 <= thr0) { u32 p = atomicAdd(&g_ccnt[R + r0], 1u); if (p < CAP) g_cand[(R + r0) * CAP + p] = (u32)c0; }
            if (d01 <= thr0) { u32 p = atomicAdd(&g_ccnt[R + r0], 1u); if (p < CAP) g_cand[(R + r0) * CAP + p] = (u32)(c0 + 1); }
            if (d10 <= thr1) { u32 p = atomicAdd(&g_ccnt[R + r1], 1u); if (p < CAP) g_cand[(R + r1) * CAP + p] = (u32)c0; }
            if (d11 <= thr1) { u32 p = atomicAdd(&g_ccnt[R + r1], 1u); if (p < CAP) g_cand[(R + r1) * CAP + p] = (u32)(c0 + 1); }
        }
    }
}

// ---------------- kernel: exact rescore + scatter (warp per row) ----------------
__global__ __launch_bounds__(256, 4)
void rescore_scatter_kernel(const float* __restrict__ z, const float* __restrict__ emb,
                            float* __restrict__ out, int out_size,
                            int zq_off, int idx_off) {
    __shared__ double wsum[8];
    const int tid  = threadIdx.x;
    const int lane = tid & 31;
    const int w    = tid >> 5;
    const int row  = blockIdx.x * 8 + w;

    const float a = g_rowa[row];
    const float* zr = z + (size_t)row * EDIM;
    u32 cnt = g_ccnt[row];
    u64 best = ~0ull;
    if (cnt <= CAP) {
        for (int c = lane; c < (int)cnt; c += 32) {
            int code = g_cand[row * CAP + c];
            const float* er = emb + (size_t)code * EDIM;
            float m = 0.0f;
            #pragma unroll 8
            for (int k = 0; k < EDIM; ++k) m = fmaf(zr[k], er[k], m);
            float d = (a + g_enorm[code]) - 2.0f * m;
            u64 p = ((u64)__float_as_uint(d) << 32) | (u32)code;
            if (p < best) best = p;
        }
    } else {
        // overflow fallback: exact scan of all 1024 codes (rare)
        for (int code = lane; code < NE; code += 32) {
            const float* er = emb + (size_t)code * EDIM;
            float m = 0.0f;
            #pragma unroll 8
            for (int k = 0; k < EDIM; ++k) m = fmaf(zr[k], er[k], m);
            float d = (a + g_enorm[code]) - 2.0f * m;
            u64 p = ((u64)__float_as_uint(d) << 32) | (u32)code;
            if (p < best) best = p;
        }
    }
    #pragma unroll
    for (int off = 16; off; off >>= 1) {
        u64 o = __shfl_xor_sync(0xffffffffu, best, off);
        if (o < best) best = o;
    }
    const int id = (int)(u32)(best & 0xffffffffull);

    // scatter: z_q straight-through, loss partial, segment sums, counts
    const float4* zr4 = reinterpret_cast<const float4*>(zr);
    const float4* er4 = reinterpret_cast<const float4*>(emb + (size_t)id * EDIM);
    double ls = 0.0;
    #pragma unroll
    for (int j = 0; j < 2; ++j) {
        int c4 = lane + 32 * j;
        float4 zv = zr4[c4];
        float4 ev = er4[c4];
        float dx = ev.x - zv.x, dy = ev.y - zv.y, dz = ev.z - zv.z, dw = ev.w - zv.w;
        if (zq_off >= 0) {
            int base = zq_off + row * EDIM + c4 * 4;
            if (base + 3 < out_size) {
                out[base + 0] = zv.x + dx;
                out[base + 1] = zv.y + dy;
                out[base + 2] = zv.z + dz;
                out[base + 3] = zv.w + dw;
            }
        }
        ls += (double)dx * dx + (double)dy * dy + (double)dz * dz + (double)dw * dw;
        int sb = id * EDIM + c4 * 4;
        atomicAdd(&g_sums[sb + 0], zv.x);
        atomicAdd(&g_sums[sb + 1], zv.y);
        atomicAdd(&g_sums[sb + 2], zv.z);
        atomicAdd(&g_sums[sb + 3], zv.w);
    }
    if (lane == 0) {
        g_idx[row] = id;
        atomicAdd(&g_counts[id], 1.0f);
        if (idx_off >= 0) {
            int p = idx_off + row;
            if (p < out_size) out[p] = (float)id;
        }
    }
    #pragma unroll
    for (int off = 16; off; off >>= 1)
        ls += __shfl_down_sync(0xffffffffu, ls, off);
    if (lane == 0) wsum[w] = ls;
    __syncthreads();
    if (tid == 0) {
        double t = 0.0;
        #pragma unroll
        for (int i = 0; i < 8; ++i) t += wsum[i];
        g_losspart[blockIdx.x] = t;
    }
}

// ---------------- kernel: m_t EMA update ---------------------------------------
__global__ void mt_kernel(const float* __restrict__ m_t, float* __restrict__ out,
                          int out_size, int mt_off) {
    int i = blockIdx.x * blockDim.x + threadIdx.x;
    if (i >= NE * EDIM || mt_off < 0) return;
    int j = i >> 8;
    float m = m_t[i];
    float val = (g_counts[j] > 0.0f) ? (m * 0.99f + g_sums[i] * 0.01f) : m;
    int p = mt_off + i;
    if (p < out_size) out[p] = val;
}

// ---------------- kernel: loss / perplexity / N_t -------------------------------
__global__ void finalize_kernel(const float* __restrict__ N_t, float* __restrict__ out,
                                int out_size, int loss_off, int perp_off, int nt_off) {
    __shared__ double red[1024];
    int tid = threadIdx.x;

    double s = 0.0;
    for (int i = tid; i < LOSSPARTS; i += 1024) s += g_losspart[i];
    red[tid] = s;
    __syncthreads();
    for (int st = 512; st > 0; st >>= 1) {
        if (tid < st) red[tid] += red[tid + st];
        __syncthreads();
    }
    double loss_sum = red[0];
    __syncthreads();

    float c = g_counts[tid];
    float em = c * (1.0f / 65536.0f);
    red[tid] = (double)(em * logf(em + 1e-10f));
    __syncthreads();
    for (int st = 512; st > 0; st >>= 1) {
        if (tid < st) red[tid] += red[tid + st];
        __syncthreads();
    }
    if (tid == 0) {
        if (loss_off >= 0 && loss_off < out_size)
            out[loss_off] = 0.25f * (float)(loss_sum / 16777216.0);
        if (perp_off >= 0 && perp_off < out_size)
            out[perp_off] = expf(-(float)red[0]);
    }
    if (nt_off >= 0) {
        float nt = N_t[tid];
        float val = (c > 0.0f) ? (nt * 0.99f + c * 0.01f) : nt;
        int p = nt_off + tid;
        if (p < out_size) out[p] = val;
    }
}

// ---------------- launcher -------------------------------------------------------
extern "C" void kernel_launch(void* const* d_in, const int* in_sizes, int n_in,
                              void* d_out, int out_size) {
    const float* z   = (const float*)d_in[0];   // [32,2048,256]
    const float* emb = (const float*)d_in[1];   // [1024,256]
    const float* N_t = (const float*)d_in[2];   // [1024]
    const float* m_t = (const float*)d_in[3];   // [1024,256]
    float* out = (float*)d_out;

    int loss_off, zq_off, idx_off, perp_off, nt_off, mt_off;
    if (out_size == NROWS * EDIM) {             // z_q_st only
        loss_off = -1; zq_off = 0; idx_off = -1; perp_off = -1; nt_off = -1; mt_off = -1;
    } else if (out_size == NROWS) {             // idx only
        loss_off = -1; zq_off = -1; idx_off = 0; perp_off = -1; nt_off = -1; mt_off = -1;
    } else {                                    // full tuple concat
        loss_off = OFF_LOSS; zq_off = OFF_ZQ; idx_off = OFF_IDX;
        perp_off = OFF_PERP; nt_off = OFF_NT; mt_off = OFF_MT;
    }

    zero_kernel<<<1024, 256>>>();
    prep_e_kernel<<<NE / 8, 256>>>(emb);
    prep_z_kernel<<<NROWS / 8, 256>>>(z);
    {
        dim3 grid(8, 512);                      // code tiles fast, row tiles slow
        argmin_mma_kernel<<<grid, 256>>>();
    }
    rescore_scatter_kernel<<<NROWS / 8, 256>>>(z, emb, out, out_size, zq_off, idx_off);
    mt_kernel<<<NE * EDIM / 256, 256>>>(m_t, out, out_size, mt_off);
    finalize_kernel<<<1, 1024>>>(N_t, out, out_size, loss_off, perp_off, nt_off);
}